// round 4
// baseline (speedup 1.0000x reference)
#include <cuda_runtime.h>
#include <cuda_bf16.h>
#include <cstdint>

// ---------------------------------------------------------------------------
// Problem constants
// ---------------------------------------------------------------------------
#define DIMC      256
#define HEADS     8
#define HEAD_DIM  32
#define HIDDEN    1024
#define SEQ       2048
#define BATCH     2
#define RPS       (BATCH * SEQ)          // 4096 rows per stream
#define TOTAL_ROWS (2 * RPS)             // 8192
#define STREAM_OFF (RPS * DIMC)

#define QK_SCALE 0.42044820762685725f    // HEAD_DIM^-0.25

// ---------------------------------------------------------------------------
// Scratch
// ---------------------------------------------------------------------------
__device__ float g_n  [TOTAL_ROWS * DIMC];
__device__ float g_qk [TOTAL_ROWS * DIMC];
__device__ float g_v  [TOTAL_ROWS * DIMC];
__device__ float g_m  [TOTAL_ROWS * DIMC];
__device__ float g_mm [TOTAL_ROWS * DIMC];
__device__ float g_h  [TOTAL_ROWS * HIDDEN];
__device__ float g_t  [TOTAL_ROWS * DIMC];

// ---------------------------------------------------------------------------
// PTX helpers
// ---------------------------------------------------------------------------
__device__ __forceinline__ uint32_t f2tf(float f) {
    uint32_t u;
    asm("cvt.rna.tf32.f32 %0, %1;" : "=r"(u) : "f"(f));
    return u;
}

__device__ __forceinline__ void mma_tf32(
    float& c0, float& c1, float& c2, float& c3,
    uint32_t a0, uint32_t a1, uint32_t a2, uint32_t a3,
    uint32_t b0, uint32_t b1)
{
    asm volatile(
        "mma.sync.aligned.m16n8k8.row.col.f32.tf32.tf32.f32 "
        "{%0,%1,%2,%3},{%4,%5,%6,%7},{%8,%9},{%0,%1,%2,%3};"
        : "+f"(c0), "+f"(c1), "+f"(c2), "+f"(c3)
        : "r"(a0), "r"(a1), "r"(a2), "r"(a3), "r"(b0), "r"(b1));
}

__device__ __forceinline__ uint32_t smem_u32(const void* p) {
    return (uint32_t)__cvta_generic_to_shared(p);
}
__device__ __forceinline__ void cp_async16(uint32_t dst, const void* src) {
    asm volatile("cp.async.cg.shared.global [%0], [%1], 16;"
                 :: "r"(dst), "l"(src));
}
__device__ __forceinline__ void cp_commit() {
    asm volatile("cp.async.commit_group;");
}
template <int N>
__device__ __forceinline__ void cp_wait() {
    asm volatile("cp.async.wait_group %0;" :: "n"(N));
}

// ---------------------------------------------------------------------------
// LayerNorm over both streams: one warp per row
// ---------------------------------------------------------------------------
__global__ __launch_bounds__(256) void ln_kernel(
    const float* __restrict__ x0, const float* __restrict__ x1,
    const float* __restrict__ w, const float* __restrict__ b,
    float* __restrict__ out)
{
    int warp = threadIdx.x >> 5, lane = threadIdx.x & 31;
    int row = blockIdx.x * 8 + warp;
    const float* xr = (row < RPS) ? x0 + (size_t)row * DIMC
                                  : x1 + (size_t)(row - RPS) * DIMC;
    float v[8];
    float sum = 0.f;
#pragma unroll
    for (int i = 0; i < 8; i++) { v[i] = xr[lane + i * 32]; sum += v[i]; }
#pragma unroll
    for (int o = 16; o; o >>= 1) sum += __shfl_xor_sync(0xffffffffu, sum, o);
    float mean = sum * (1.f / 256.f);
    float vs = 0.f;
#pragma unroll
    for (int i = 0; i < 8; i++) { float d = v[i] - mean; vs += d * d; }
#pragma unroll
    for (int o = 16; o; o >>= 1) vs += __shfl_xor_sync(0xffffffffu, vs, o);
    float rstd = rsqrtf(vs * (1.f / 256.f) + 1e-5f);
    float* orow = out + (size_t)row * DIMC;
#pragma unroll
    for (int i = 0; i < 8; i++) {
        int c = lane + i * 32;
        orow[c] = (v[i] - mean) * rstd * w[c] + b[c];
    }
}

// ---------------------------------------------------------------------------
// Final: out = x + gamma * LayerNorm(t), both streams
// ---------------------------------------------------------------------------
__global__ __launch_bounds__(256) void final_kernel(
    const float* __restrict__ t,
    const float* __restrict__ x0, const float* __restrict__ x1,
    const float* __restrict__ w, const float* __restrict__ b,
    const float* __restrict__ gamma, float* __restrict__ out)
{
    int warp = threadIdx.x >> 5, lane = threadIdx.x & 31;
    int row = blockIdx.x * 8 + warp;
    const float* tr = t + (size_t)row * DIMC;
    const float* xr = (row < RPS) ? x0 + (size_t)row * DIMC
                                  : x1 + (size_t)(row - RPS) * DIMC;
    float v[8];
    float sum = 0.f;
#pragma unroll
    for (int i = 0; i < 8; i++) { v[i] = tr[lane + i * 32]; sum += v[i]; }
#pragma unroll
    for (int o = 16; o; o >>= 1) sum += __shfl_xor_sync(0xffffffffu, sum, o);
    float mean = sum * (1.f / 256.f);
    float vs = 0.f;
#pragma unroll
    for (int i = 0; i < 8; i++) { float d = v[i] - mean; vs += d * d; }
#pragma unroll
    for (int o = 16; o; o >>= 1) vs += __shfl_xor_sync(0xffffffffu, vs, o);
    float rstd = rsqrtf(vs * (1.f / 256.f) + 1e-5f);
    float* orow = out + (size_t)row * DIMC;
#pragma unroll
    for (int i = 0; i < 8; i++) {
        int c = lane + i * 32;
        float ln = (v[i] - mean) * rstd * w[c] + b[c];
        orow[c] = xr[c] + gamma[c] * ln;
    }
}

// ---------------------------------------------------------------------------
// cp.async double-buffered tf32 GEMM.
// C[M,Nout] = act(alpha * A[M,K] @ B[Nout,K]^T + bias)
// BM=BN=128, BK=32, 256 threads (8 warps 2x4), warp tile 64x32.
// DUAL: grid.x spans 2*Nout cols; first half -> B0/C0/alpha0, second -> B1/C1/alpha1
// CAT : A column kk<DIMC comes from x (A0/A1 per stream row), else from Am.
// Dynamic smem: 2 stages x (A 128x36 + B 128x36) floats = 73728 B.
// ---------------------------------------------------------------------------
#define GEMM_SMEM (2 * 2 * 128 * 36 * 4)

template <bool GELU, bool HAS_BIAS, bool DUAL, bool CAT>
__global__ __launch_bounds__(256) void gemm_tc(
    const float* __restrict__ A0, const float* __restrict__ A1,
    const float* __restrict__ Am,
    const float* __restrict__ B0, const float* __restrict__ B1,
    const float* __restrict__ bias,
    float* __restrict__ C0, float* __restrict__ C1,
    int Nout, int K, float alpha0, float alpha1)
{
    constexpr int BK = 32;
    extern __shared__ float dsm[];
    float* AsBase = dsm;               // [2][128][36]
    float* BsBase = dsm + 2 * 128 * 36;

    int tid = threadIdx.x;
    int wid = tid >> 5, lane = tid & 31;
    int grp = lane >> 2, tig = lane & 3;
    int warp_m = wid >> 2, warp_n = wid & 3;
    int m0 = blockIdx.y * 128;
    int n0 = blockIdx.x * 128;

    const float* Bp;
    float* Cp;
    float alpha;
    if (DUAL) {
        if (n0 < Nout) { Bp = B0 + (size_t)n0 * K; Cp = C0; alpha = alpha0; }
        else { n0 -= Nout; Bp = B1 + (size_t)n0 * K; Cp = C1; alpha = alpha1; }
    } else {
        Bp = B0 + (size_t)n0 * K; Cp = C0; alpha = alpha0;
    }

    float acc[4][4][4] = {};
    int KT = K / BK;

    // --- stage loader ---
    auto load_stage = [&](int ktb, int s) {
        float* Ad = AsBase + s * (128 * 36);
        float* Bd = BsBase + s * (128 * 36);
#pragma unroll
        for (int j = 0; j < 4; j++) {
            int idx = tid + j * 256;
            int r = idx >> 3, c4 = idx & 7;
            int kk = ktb + c4 * 4;
            const float* src;
            if (CAT) {
                int row = m0 + r;
                if (kk < DIMC) {
                    const float* x = (row < RPS) ? A0 + (size_t)row * DIMC
                                                 : A1 + (size_t)(row - RPS) * DIMC;
                    src = x + kk;
                } else {
                    src = Am + (size_t)row * DIMC + (kk - DIMC);
                }
            } else {
                src = A0 + (size_t)(m0 + r) * K + kk;
            }
            cp_async16(smem_u32(&Ad[r * 36 + c4 * 4]), src);
        }
#pragma unroll
        for (int j = 0; j < 4; j++) {
            int idx = tid + j * 256;
            int r = idx >> 3, c4 = idx & 7;
            cp_async16(smem_u32(&Bd[r * 36 + c4 * 4]),
                       Bp + (size_t)r * K + ktb + c4 * 4);
        }
        cp_commit();
    };

    load_stage(0, 0);

    for (int kt = 0; kt < KT; kt++) {
        int s = kt & 1;
        if (kt + 1 < KT) { load_stage((kt + 1) * BK, s ^ 1); cp_wait<1>(); }
        else             { cp_wait<0>(); }
        __syncthreads();

        const float* Ad = AsBase + s * (128 * 36);
        const float* Bd = BsBase + s * (128 * 36);
#pragma unroll
        for (int ks = 0; ks < 4; ks++) {
            int k0 = ks * 8;
            uint32_t af[4][4], bf[4][2];
#pragma unroll
            for (int mt = 0; mt < 4; mt++) {
                int mr = warp_m * 64 + mt * 16;
                af[mt][0] = f2tf(Ad[(mr + grp    ) * 36 + k0 + tig    ]);
                af[mt][1] = f2tf(Ad[(mr + grp + 8) * 36 + k0 + tig    ]);
                af[mt][2] = f2tf(Ad[(mr + grp    ) * 36 + k0 + tig + 4]);
                af[mt][3] = f2tf(Ad[(mr + grp + 8) * 36 + k0 + tig + 4]);
            }
#pragma unroll
            for (int nt = 0; nt < 4; nt++) {
                int nr = warp_n * 32 + nt * 8;
                bf[nt][0] = f2tf(Bd[(nr + grp) * 36 + k0 + tig    ]);
                bf[nt][1] = f2tf(Bd[(nr + grp) * 36 + k0 + tig + 4]);
            }
#pragma unroll
            for (int mt = 0; mt < 4; mt++)
#pragma unroll
                for (int nt = 0; nt < 4; nt++)
                    mma_tf32(acc[mt][nt][0], acc[mt][nt][1],
                             acc[mt][nt][2], acc[mt][nt][3],
                             af[mt][0], af[mt][1], af[mt][2], af[mt][3],
                             bf[nt][0], bf[nt][1]);
        }
        __syncthreads();
    }

#pragma unroll
    for (int mt = 0; mt < 4; mt++) {
        int mr = m0 + warp_m * 64 + mt * 16;
#pragma unroll
        for (int nt = 0; nt < 4; nt++) {
            int nc = n0 + warp_n * 32 + nt * 8 + 2 * tig;
            float b0 = 0.f, b1 = 0.f;
            if (HAS_BIAS) { b0 = bias[nc]; b1 = bias[nc + 1]; }
            float v0 = acc[mt][nt][0] * alpha + b0;
            float v1 = acc[mt][nt][1] * alpha + b1;
            float v2 = acc[mt][nt][2] * alpha + b0;
            float v3 = acc[mt][nt][3] * alpha + b1;
            if (GELU) {
                v0 = 0.5f * v0 * (1.f + erff(v0 * 0.70710678118654752f));
                v1 = 0.5f * v1 * (1.f + erff(v1 * 0.70710678118654752f));
                v2 = 0.5f * v2 * (1.f + erff(v2 * 0.70710678118654752f));
                v3 = 0.5f * v3 * (1.f + erff(v3 * 0.70710678118654752f));
            }
            *reinterpret_cast<float2*>(&Cp[(size_t)(mr + grp) * Nout + nc]) =
                make_float2(v0, v1);
            *reinterpret_cast<float2*>(&Cp[(size_t)(mr + grp + 8) * Nout + nc]) =
                make_float2(v2, v3);
        }
    }
}

// ---------------------------------------------------------------------------
// tf32 flash attention, both directions in one launch.
// Block: 128 threads (4 warps), 64 queries, key chunks of 64, cp.async 2-stage.
// grid: (SEQ/64, HEADS, 2*BATCH); z: b = z&1, dir = z>>1
// Dynamic smem: K 2x64x36 + V 2x64x40 + P 4x16x68 floats = 56320 B.
// ---------------------------------------------------------------------------
#define FLASH_SMEM ((2*64*36 + 2*64*40 + 4*16*68) * 4)

__global__ __launch_bounds__(128) void flash_tc(
    const float* __restrict__ qkb, const float* __restrict__ vb,
    float* __restrict__ mb)
{
    extern __shared__ float dsm[];
    float* KsB = dsm;                      // [2][64][36]
    float* VsB = dsm + 2 * 64 * 36;        // [2][64][40]
    float* PsB = VsB + 2 * 64 * 40;        // [4][16][68]

    int tid = threadIdx.x;
    int wid = tid >> 5, lane = tid & 31;
    int grp = lane >> 2, tig = lane & 3;
    int h = blockIdx.y;
    int z = blockIdx.z;
    int b = z & 1, dir = z >> 1;

    const float* Q  = dir ? qkb + STREAM_OFF : qkb;
    const float* Kp = dir ? qkb : qkb + STREAM_OFF;
    const float* Vp = dir ? vb  : vb  + STREAM_OFF;
    float*       O  = dir ? mb + STREAM_OFF : mb;

    size_t brow = (size_t)b * SEQ;
    int q0 = blockIdx.x * 64 + wid * 16;
    float* Ps = PsB + wid * (16 * 68);

    // register-resident Q fragments
    uint32_t qa[4][4];
    const float* Qb = Q + (brow + q0) * DIMC + h * HEAD_DIM;
#pragma unroll
    for (int ks = 0; ks < 4; ks++) {
        qa[ks][0] = f2tf(Qb[(size_t)(grp    ) * DIMC + ks * 8 + tig    ]);
        qa[ks][1] = f2tf(Qb[(size_t)(grp + 8) * DIMC + ks * 8 + tig    ]);
        qa[ks][2] = f2tf(Qb[(size_t)(grp    ) * DIMC + ks * 8 + tig + 4]);
        qa[ks][3] = f2tf(Qb[(size_t)(grp + 8) * DIMC + ks * 8 + tig + 4]);
    }

    auto load_chunk = [&](int kc, int s) {
        float* Kd = KsB + s * (64 * 36);
        float* Vd = VsB + s * (64 * 40);
#pragma unroll
        for (int j = 0; j < 4; j++) {
            int idx = tid + j * 128;
            int r = idx >> 3, c4 = idx & 7;
            size_t g = (brow + (size_t)kc * 64 + r) * DIMC + h * HEAD_DIM + c4 * 4;
            cp_async16(smem_u32(&Kd[r * 36 + c4 * 4]), Kp + g);
            cp_async16(smem_u32(&Vd[r * 40 + c4 * 4]), Vp + g);
        }
        cp_commit();
    };

    float oacc[4][4] = {};
    float mr0 = -1e30f, mr1 = -1e30f, l0 = 0.f, l1 = 0.f;
    constexpr int NC = SEQ / 64;

    load_chunk(0, 0);

    for (int kc = 0; kc < NC; kc++) {
        int s = kc & 1;
        if (kc + 1 < NC) { load_chunk(kc + 1, s ^ 1); cp_wait<1>(); }
        else             { cp_wait<0>(); }
        __syncthreads();

        const float* Kd = KsB + s * (64 * 36);
        const float* Vd = VsB + s * (64 * 40);

        // S = Q @ K^T
        float sf[8][4] = {};
#pragma unroll
        for (int ks = 0; ks < 4; ks++) {
            int k0 = ks * 8;
#pragma unroll
            for (int nt = 0; nt < 8; nt++) {
                uint32_t b0 = f2tf(Kd[(nt * 8 + grp) * 36 + k0 + tig    ]);
                uint32_t b1 = f2tf(Kd[(nt * 8 + grp) * 36 + k0 + tig + 4]);
                mma_tf32(sf[nt][0], sf[nt][1], sf[nt][2], sf[nt][3],
                         qa[ks][0], qa[ks][1], qa[ks][2], qa[ks][3], b0, b1);
            }
        }

        // online softmax (rows grp, grp+8; reduce over tig quad)
        float cm0 = -1e30f, cm1 = -1e30f;
#pragma unroll
        for (int nt = 0; nt < 8; nt++) {
            cm0 = fmaxf(cm0, fmaxf(sf[nt][0], sf[nt][1]));
            cm1 = fmaxf(cm1, fmaxf(sf[nt][2], sf[nt][3]));
        }
        cm0 = fmaxf(cm0, __shfl_xor_sync(0xffffffffu, cm0, 1));
        cm0 = fmaxf(cm0, __shfl_xor_sync(0xffffffffu, cm0, 2));
        cm1 = fmaxf(cm1, __shfl_xor_sync(0xffffffffu, cm1, 1));
        cm1 = fmaxf(cm1, __shfl_xor_sync(0xffffffffu, cm1, 2));
        float nm0 = fmaxf(mr0, cm0), nm1 = fmaxf(mr1, cm1);
        float corr0 = __expf(mr0 - nm0), corr1 = __expf(mr1 - nm1);

        float sum0 = 0.f, sum1 = 0.f;
#pragma unroll
        for (int nt = 0; nt < 8; nt++) {
            float p0 = __expf(sf[nt][0] - nm0);
            float p1 = __expf(sf[nt][1] - nm0);
            float p2 = __expf(sf[nt][2] - nm1);
            float p3 = __expf(sf[nt][3] - nm1);
            sum0 += p0 + p1;
            sum1 += p2 + p3;
            *reinterpret_cast<uint2*>(&Ps[grp * 68 + nt * 8 + 2 * tig]) =
                make_uint2(f2tf(p0), f2tf(p1));
            *reinterpret_cast<uint2*>(&Ps[(grp + 8) * 68 + nt * 8 + 2 * tig]) =
                make_uint2(f2tf(p2), f2tf(p3));
        }
        sum0 += __shfl_xor_sync(0xffffffffu, sum0, 1);
        sum0 += __shfl_xor_sync(0xffffffffu, sum0, 2);
        sum1 += __shfl_xor_sync(0xffffffffu, sum1, 1);
        sum1 += __shfl_xor_sync(0xffffffffu, sum1, 2);
        l0 = l0 * corr0 + sum0;
        l1 = l1 * corr1 + sum1;
        mr0 = nm0; mr1 = nm1;

#pragma unroll
        for (int nt = 0; nt < 4; nt++) {
            oacc[nt][0] *= corr0; oacc[nt][1] *= corr0;
            oacc[nt][2] *= corr1; oacc[nt][3] *= corr1;
        }
        __syncwarp();

        // O += P @ V
        const uint32_t* Pu = reinterpret_cast<const uint32_t*>(Ps);
#pragma unroll
        for (int ks = 0; ks < 8; ks++) {
            int k0 = ks * 8;
            uint32_t a0 = Pu[(grp    ) * 68 + k0 + tig    ];
            uint32_t a1 = Pu[(grp + 8) * 68 + k0 + tig    ];
            uint32_t a2 = Pu[(grp    ) * 68 + k0 + tig + 4];
            uint32_t a3 = Pu[(grp + 8) * 68 + k0 + tig + 4];
#pragma unroll
            for (int nt = 0; nt < 4; nt++) {
                uint32_t b0 = f2tf(Vd[(k0 + tig    ) * 40 + nt * 8 + grp]);
                uint32_t b1 = f2tf(Vd[(k0 + tig + 4) * 40 + nt * 8 + grp]);
                mma_tf32(oacc[nt][0], oacc[nt][1], oacc[nt][2], oacc[nt][3],
                         a0, a1, a2, a3, b0, b1);
            }
        }
        __syncthreads();
    }

    float inv0 = 1.f / l0, inv1 = 1.f / l1;
    float* Ob = O + (brow + q0) * DIMC + h * HEAD_DIM;
#pragma unroll
    for (int nt = 0; nt < 4; nt++) {
        int c = nt * 8 + 2 * tig;
        *reinterpret_cast<float2*>(&Ob[(size_t)(grp    ) * DIMC + c]) =
            make_float2(oacc[nt][0] * inv0, oacc[nt][1] * inv0);
        *reinterpret_cast<float2*>(&Ob[(size_t)(grp + 8) * DIMC + c]) =
            make_float2(oacc[nt][2] * inv1, oacc[nt][3] * inv1);
    }
}

// ---------------------------------------------------------------------------
// Launch
// ---------------------------------------------------------------------------
extern "C" void kernel_launch(void* const* d_in, const int* in_sizes, int n_in,
                              void* d_out, int out_size)
{
    const float* x0      = (const float*)d_in[0];
    const float* x1      = (const float*)d_in[1];
    const float* qk_w    = (const float*)d_in[2];
    const float* v_w     = (const float*)d_in[3];
    const float* merge_w = (const float*)d_in[4];
    const float* ln1_w   = (const float*)d_in[5];
    const float* ln1_b   = (const float*)d_in[6];
    const float* ln2_w   = (const float*)d_in[7];
    const float* ln2_b   = (const float*)d_in[8];
    const float* fc1_w   = (const float*)d_in[9];
    const float* fc1_b   = (const float*)d_in[10];
    const float* fc2_w   = (const float*)d_in[11];
    const float* fc2_b   = (const float*)d_in[12];
    const float* gamma   = (const float*)d_in[13];
    float* out = (float*)d_out;

    float *nbuf, *qk, *v, *m, *mm, *h, *t;
    cudaGetSymbolAddress((void**)&nbuf, g_n);
    cudaGetSymbolAddress((void**)&qk,   g_qk);
    cudaGetSymbolAddress((void**)&v,    g_v);
    cudaGetSymbolAddress((void**)&m,    g_m);
    cudaGetSymbolAddress((void**)&mm,   g_mm);
    cudaGetSymbolAddress((void**)&h,    g_h);
    cudaGetSymbolAddress((void**)&t,    g_t);

    // opt-in dynamic smem (> 48 KB)
    cudaFuncSetAttribute(gemm_tc<false, false, true, false>,
                         cudaFuncAttributeMaxDynamicSharedMemorySize, GEMM_SMEM);
    cudaFuncSetAttribute(gemm_tc<false, false, false, false>,
                         cudaFuncAttributeMaxDynamicSharedMemorySize, GEMM_SMEM);
    cudaFuncSetAttribute(gemm_tc<true, true, false, true>,
                         cudaFuncAttributeMaxDynamicSharedMemorySize, GEMM_SMEM);
    cudaFuncSetAttribute(gemm_tc<false, true, false, false>,
                         cudaFuncAttributeMaxDynamicSharedMemorySize, GEMM_SMEM);
    cudaFuncSetAttribute(flash_tc,
                         cudaFuncAttributeMaxDynamicSharedMemorySize, FLASH_SMEM);

    // 1. LayerNorm1 (both streams, one launch)
    ln_kernel<<<TOTAL_ROWS / 8, 256>>>(x0, x1, ln1_w, ln1_b, nbuf);

    // 2. Fused qk+v projection (dual-output GEMM, 256 CTAs)
    dim3 gP2(2 * DIMC / 128, TOTAL_ROWS / 128);
    gemm_tc<false, false, true, false><<<gP2, 256, GEMM_SMEM>>>(
        nbuf, nullptr, nullptr, qk_w, v_w, nullptr, qk, v,
        DIMC, DIMC, QK_SCALE, 1.f);

    // 3. Flash attention, both directions in one launch
    dim3 gF(SEQ / 64, HEADS, 2 * BATCH);
    flash_tc<<<gF, 128, FLASH_SMEM>>>(qk, v, m);

    // 4. Merge projection
    dim3 gP(DIMC / 128, TOTAL_ROWS / 128);
    gemm_tc<false, false, false, false><<<gP, 256, GEMM_SMEM>>>(
        m, nullptr, nullptr, merge_w, nullptr, nullptr, mm, nullptr,
        DIMC, DIMC, 1.f, 1.f);

    // 5. fc1 + exact GELU, concat fused into A loader
    dim3 gF1(HIDDEN / 128, TOTAL_ROWS / 128);
    gemm_tc<true, true, false, true><<<gF1, 256, GEMM_SMEM>>>(
        x0, x1, mm, fc1_w, nullptr, fc1_b, h, nullptr,
        HIDDEN, 2 * DIMC, 1.f, 1.f);

    // 6. fc2
    gemm_tc<false, true, false, false><<<gP, 256, GEMM_SMEM>>>(
        h, nullptr, nullptr, fc2_w, nullptr, fc2_b, t, nullptr,
        DIMC, HIDDEN, 1.f, 1.f);

    // 7. Residual + gamma * LN2 (both streams)
    final_kernel<<<TOTAL_ROWS / 8, 256>>>(t, x0, x1, ln2_w, ln2_b, gamma, out);
}